// round 14
// baseline (speedup 1.0000x reference)
#include <cuda_runtime.h>
#include <cstdint>

// HashEmbedding: B*L=819200 tokens, H=2, E=64, out=[emb(64), pv0, pv1] f32
// d_in: words int32[819200], hash_table int32[1000000,2],
//       W f32[100000,64], P f32[1000000,2]

static constexpr int NTOK  = 16384 * 50;   // 819200
static constexpr int EMBED = 64;
static constexpr int OUTW  = EMBED + 2;    // 66
static constexpr int TPW   = 8;            // tokens per warp
static constexpr int TPB   = 256;
static constexpr int WPB   = TPB / 32;     // 8 warps per block

__global__ void __launch_bounds__(TPB)
hash_embedding_kernel(const int*    __restrict__ words,
                      const int2*   __restrict__ hash_table,
                      const float*  __restrict__ W,
                      const float2* __restrict__ P2,
                      float*        __restrict__ out)
{
    // Landing buffer in SMEM instead of registers: 16 rows x 256B per warp.
    // Rows 0..7 = h.x rows of tokens 0..7; rows 8..15 = h.y rows.
    __shared__ float sbuf[WPB][16][EMBED];            // 8 * 16 * 256B = 32KB

    const int wid  = threadIdx.x >> 5;
    const int lane = threadIdx.x & 31;
    const int warp = blockIdx.x * WPB + wid;
    const int base = warp * TPW;
    if (base >= NTOK) return;
    const float* Pf = reinterpret_cast<const float*>(P2);

    // ---- Distributed scalar phase (R7-proven): lane t (mod 8) owns token
    // base+t; replicated addrs dedup in-warp -> one LDG per stage / 8 tokens. ----
    const int    tok = base + (lane & 7);
    const int    w   = __ldg(&words[tok]);
    const int2   h   = __ldg(&hash_table[w]);
    const float2 pwv = __ldg(&P2[w]);

    if (lane < TPW) {
        float2 pv;
        pv.x = __ldg(&Pf[(size_t)h.x * 2 + 0]);
        pv.y = __ldg(&Pf[(size_t)h.y * 2 + 1]);
        *reinterpret_cast<float2*>(out + (size_t)tok * OUTW + EMBED) = pv;
    }

    // ---- Burst 16 W-row gathers via cp.async (no landing registers):
    // 8B/lane, coalesced 256B rows, all 16 in flight per warp. ----
    const uint32_t sbase =
        (uint32_t)__cvta_generic_to_shared(&sbuf[wid][0][0]) + lane * 8u;
#pragma unroll
    for (int t = 0; t < TPW; t++) {
        const int hx = __shfl_sync(0xffffffffu, h.x, t);
        const int hy = __shfl_sync(0xffffffffu, h.y, t);
        const float* gx = W + (size_t)hx * EMBED + lane * 2;
        const float* gy = W + (size_t)hy * EMBED + lane * 2;
        const uint32_t sx = sbase + (uint32_t)(t       * EMBED * 4);
        const uint32_t sy = sbase + (uint32_t)((8 + t) * EMBED * 4);
        asm volatile("cp.async.ca.shared.global [%0], [%1], 8;\n"
                     :: "r"(sx), "l"(gx) : "memory");
        asm volatile("cp.async.ca.shared.global [%0], [%1], 8;\n"
                     :: "r"(sy), "l"(gy) : "memory");
    }
    asm volatile("cp.async.commit_group;\n" ::: "memory");
    asm volatile("cp.async.wait_group 0;\n" ::: "memory");
    // Each lane reads back exactly the 8B it copied: same-thread data,
    // wait_group orders it; no warp/block barrier needed.

    // ---- Consume from SMEM (LDS.64, conflict-free), combine, store. ----
#pragma unroll
    for (int t = 0; t < TPW; t++) {
        const float px = __shfl_sync(0xffffffffu, pwv.x, t);
        const float py = __shfl_sync(0xffffffffu, pwv.y, t);
        const float2 a = *reinterpret_cast<const float2*>(&sbuf[wid][t][lane * 2]);
        const float2 b = *reinterpret_cast<const float2*>(&sbuf[wid][8 + t][lane * 2]);
        float2 e;
        e.x = fmaf(a.x, px, b.x * py);
        e.y = fmaf(a.y, px, b.y * py);
        float* o = out + (size_t)(base + t) * OUTW;   // 264B stride, 8B aligned
        reinterpret_cast<float2*>(o)[lane] = e;       // cols 0..63
    }
}

extern "C" void kernel_launch(void* const* d_in, const int* in_sizes, int n_in,
                              void* d_out, int out_size)
{
    const int*    words      = (const int*)d_in[0];
    const int2*   hash_table = (const int2*)d_in[1];
    const float*  W          = (const float*)d_in[2];
    const float2* P          = (const float2*)d_in[3];
    float*        out        = (float*)d_out;

    const int tokens_per_block = WPB * TPW;                               // 64
    const int blocks = (NTOK + tokens_per_block - 1) / tokens_per_block;  // 12800
    hash_embedding_kernel<<<blocks, TPB>>>(words, hash_table, W, P, out);
}

// round 15
// speedup vs baseline: 1.1281x; 1.1281x over previous
#include <cuda_runtime.h>
#include <cstdint>

// HashEmbedding: B*L=819200 tokens, H=2, E=64, out=[emb(64), pv0, pv1] f32
// d_in: words int32[819200], hash_table int32[1000000,2],
//       W f32[100000,64], P f32[1000000,2]

static constexpr int NTOK  = 16384 * 50;   // 819200
static constexpr int EMBED = 64;
static constexpr int OUTW  = EMBED + 2;    // 66
static constexpr int GRP   = 8;            // tokens per group
static constexpr int TPW   = 16;           // two groups per warp
static constexpr int TPB   = 256;

// 48-reg ceiling (5 blocks/SM, 62.5% occ): lets ptxas hoist group-1 gathers
// above group-0 consume (all scalars are pre-resident, gathers independent),
// pushing in-flight loads toward ~24 while a0/b0 regs free as consumed.
__global__ void __launch_bounds__(TPB, 5)
hash_embedding_kernel(const int*    __restrict__ words,
                      const int2*   __restrict__ hash_table,
                      const float*  __restrict__ W,
                      const float2* __restrict__ P2,
                      float*        __restrict__ out)
{
    const int warp = (blockIdx.x * blockDim.x + threadIdx.x) >> 5;
    const int lane = threadIdx.x & 31;
    const int base = warp * TPW;
    if (base >= NTOK) return;
    const float* Pf = reinterpret_cast<const float*>(P2);

    // ---- Scalar phase over 16 tokens: lane t (mod 16) owns token base+t.
    // Replicated addrs dedup in-warp: one LDG per stage / 16 tokens. ----
    const int    tok = base + (lane & 15);
    const int    w   = __ldg(&words[tok]);
    const int2   h   = __ldg(&hash_table[w]);
    const float2 pwv = __ldg(&P2[w]);

    if (lane < TPW) {  // pvals: one gather + one scattered store, 16 tokens
        float2 pv;
        pv.x = __ldg(&Pf[(size_t)h.x * 2 + 0]);
        pv.y = __ldg(&Pf[(size_t)h.y * 2 + 1]);
        *reinterpret_cast<float2*>(out + (size_t)tok * OUTW + EMBED) = pv;
    }

    // ---- Gather BOTH groups' W rows before consuming either: the 32 loads
    // are mutually independent; ptxas schedules them under the reg budget. ----
    float2 a0[GRP], b0[GRP], a1[GRP], b1[GRP];
#pragma unroll
    for (int t = 0; t < GRP; t++) {
        const int hx = __shfl_sync(0xffffffffu, h.x, t);
        const int hy = __shfl_sync(0xffffffffu, h.y, t);
        a0[t] = __ldg(reinterpret_cast<const float2*>(W + (size_t)hx * EMBED) + lane);
        b0[t] = __ldg(reinterpret_cast<const float2*>(W + (size_t)hy * EMBED) + lane);
    }
#pragma unroll
    for (int t = 0; t < GRP; t++) {
        const int hx = __shfl_sync(0xffffffffu, h.x, GRP + t);
        const int hy = __shfl_sync(0xffffffffu, h.y, GRP + t);
        a1[t] = __ldg(reinterpret_cast<const float2*>(W + (size_t)hx * EMBED) + lane);
        b1[t] = __ldg(reinterpret_cast<const float2*>(W + (size_t)hy * EMBED) + lane);
    }

    // ---- Consume group 0 (frees a0/b0 regs for in-flight a1/b1), store. ----
#pragma unroll
    for (int t = 0; t < GRP; t++) {
        const float px = __shfl_sync(0xffffffffu, pwv.x, t);
        const float py = __shfl_sync(0xffffffffu, pwv.y, t);
        float2 e;
        e.x = fmaf(a0[t].x, px, b0[t].x * py);
        e.y = fmaf(a0[t].y, px, b0[t].y * py);
        float* o = out + (size_t)(base + t) * OUTW;
        reinterpret_cast<float2*>(o)[lane] = e;
    }
    // ---- Consume group 1, store. ----
#pragma unroll
    for (int t = 0; t < GRP; t++) {
        const float px = __shfl_sync(0xffffffffu, pwv.x, GRP + t);
        const float py = __shfl_sync(0xffffffffu, pwv.y, GRP + t);
        float2 e;
        e.x = fmaf(a1[t].x, px, b1[t].x * py);
        e.y = fmaf(a1[t].y, px, b1[t].y * py);
        float* o = out + (size_t)(base + GRP + t) * OUTW;
        reinterpret_cast<float2*>(o)[lane] = e;
    }
}

extern "C" void kernel_launch(void* const* d_in, const int* in_sizes, int n_in,
                              void* d_out, int out_size)
{
    const int*    words      = (const int*)d_in[0];
    const int2*   hash_table = (const int2*)d_in[1];
    const float*  W          = (const float*)d_in[2];
    const float2* P          = (const float2*)d_in[3];
    float*        out        = (float*)d_out;

    const int tokens_per_block = (TPB / 32) * TPW;                        // 128
    const int blocks = (NTOK + tokens_per_block - 1) / tokens_per_block;  // 6400
    hash_embedding_kernel<<<blocks, TPB>>>(words, hash_table, W, P, out);
}

// round 16
// speedup vs baseline: 1.5309x; 1.3571x over previous
#include <cuda_runtime.h>
#include <cstdint>

// HashEmbedding: B*L=819200 tokens, H=2, E=64, out=[emb(64), pv0, pv1] f32
// d_in: words int32[819200], hash_table int32[1000000,2],
//       W f32[100000,64], P f32[1000000,2]

static constexpr int NTOK  = 16384 * 50;   // 819200
static constexpr int EMBED = 64;
static constexpr int OUTW  = EMBED + 2;    // 66
static constexpr int TPW   = 8;            // tokens per warp (R7-proven)
static constexpr int TPB   = 256;

__global__ void __launch_bounds__(TPB)
hash_embedding_kernel(const int*    __restrict__ words,
                      const int2*   __restrict__ hash_table,
                      const float*  __restrict__ W,
                      const float2* __restrict__ P2,
                      float*        __restrict__ out)
{
    const int warp = (blockIdx.x * blockDim.x + threadIdx.x) >> 5;
    const int lane = threadIdx.x & 31;
    const int base = warp * TPW;
    if (base >= NTOK) return;
    const float* Pf = reinterpret_cast<const float*>(P2);

    // ---- Distributed scalar phase (R7): lane t (mod 8) owns token base+t;
    // replicated addrs dedup in-warp -> one LDG per stage covers 8 tokens. ----
    const int    tok = base + (lane & 7);
    const int    w   = __ldg(&words[tok]);
    const int2   h   = __ldg(&hash_table[w]);
    const float2 pwv = __ldg(&P2[w]);

    if (lane < TPW) {
        float2 pv;
        pv.x = __ldg(&Pf[(size_t)h.x * 2 + 0]);
        pv.y = __ldg(&Pf[(size_t)h.y * 2 + 1]);
        *reinterpret_cast<float2*>(out + (size_t)tok * OUTW + EMBED) = pv;
    }

    // ---- Burst-issue 32 W-row gathers as LDG.32: each instruction moves
    // exactly 128B = 1 L1 wavefront @ ~1.0 cyc (vs LDG.64's 2 wf @ ~2.07
    // within-instruction replay). Same bytes/sectors/registers, ~2x fewer
    // l1tex cycles. Lane i covers elems i (lo half) and 32+i (hi half) —
    // non-adjacent per thread, so ptxas cannot re-fuse into LDG.64. ----
    float a_lo[TPW], a_hi[TPW], b_lo[TPW], b_hi[TPW];
#pragma unroll
    for (int t = 0; t < TPW; t++) {
        const int hx = __shfl_sync(0xffffffffu, h.x, t);
        const int hy = __shfl_sync(0xffffffffu, h.y, t);
        const float* rx = W + (size_t)hx * EMBED;
        const float* ry = W + (size_t)hy * EMBED;
        a_lo[t] = __ldg(rx + lane);
        a_hi[t] = __ldg(rx + 32 + lane);
        b_lo[t] = __ldg(ry + lane);
        b_hi[t] = __ldg(ry + 32 + lane);
    }

    // ---- Consume in order (frees regs early); stores as 2x STG.32
    // (128B = 1 wavefront each). ----
#pragma unroll
    for (int t = 0; t < TPW; t++) {
        const float px = __shfl_sync(0xffffffffu, pwv.x, t);
        const float py = __shfl_sync(0xffffffffu, pwv.y, t);
        const float e_lo = fmaf(a_lo[t], px, b_lo[t] * py);
        const float e_hi = fmaf(a_hi[t], px, b_hi[t] * py);
        float* o = out + (size_t)(base + t) * OUTW;   // 264B stride
        o[lane]      = e_lo;                          // cols 0..31
        o[32 + lane] = e_hi;                          // cols 32..63
    }
}

extern "C" void kernel_launch(void* const* d_in, const int* in_sizes, int n_in,
                              void* d_out, int out_size)
{
    const int*    words      = (const int*)d_in[0];
    const int2*   hash_table = (const int2*)d_in[1];
    const float*  W          = (const float*)d_in[2];
    const float2* P          = (const float2*)d_in[3];
    float*        out        = (float*)d_out;

    const int tokens_per_block = (TPB / 32) * TPW;                        // 64
    const int blocks = (NTOK + tokens_per_block - 1) / tokens_per_block;  // 12800
    hash_embedding_kernel<<<blocks, TPB>>>(words, hash_table, W, P, out);
}

// round 17
// speedup vs baseline: 1.7378x; 1.1351x over previous
#include <cuda_runtime.h>
#include <cstdint>

// HashEmbedding: B*L=819200 tokens, H=2, E=64, out=[emb(64), pv0, pv1] f32
// d_in: words int32[819200], hash_table int32[1000000,2],
//       W f32[100000,64], P f32[1000000,2]
//
// R7 shape (proven best: 32 regs, ~84% occ) + streaming (.cs) output stores.

static constexpr int NTOK  = 16384 * 50;   // 819200
static constexpr int EMBED = 64;
static constexpr int OUTW  = EMBED + 2;    // 66
static constexpr int TPW   = 8;            // tokens per warp
static constexpr int TPB   = 256;

__device__ __forceinline__ void stg_cs_f2(float* p, float x, float y) {
    asm volatile("st.global.cs.v2.f32 [%0], {%1, %2};"
                 :: "l"(p), "f"(x), "f"(y) : "memory");
}

__global__ void __launch_bounds__(TPB)
hash_embedding_kernel(const int*    __restrict__ words,
                      const int2*   __restrict__ hash_table,
                      const float*  __restrict__ W,
                      const float2* __restrict__ P2,
                      float*        __restrict__ out)
{
    const int warp = (blockIdx.x * blockDim.x + threadIdx.x) >> 5;
    const int lane = threadIdx.x & 31;
    const int base = warp * TPW;
    if (base >= NTOK) return;
    const float* Pf = reinterpret_cast<const float*>(P2);

    // ---- Distributed scalar phase: lane t (mod 8) owns token base+t.
    // Replicated addrs dedup in-warp: one LDG per stage covers 8 tokens. ----
    const int    tok = base + (lane & 7);
    const int    w   = __ldg(&words[tok]);
    const int2   h   = __ldg(&hash_table[w]);
    const float2 pwv = __ldg(&P2[w]);

    if (lane < TPW) {
        float2 pv;
        pv.x = __ldg(&Pf[(size_t)h.x * 2 + 0]);
        pv.y = __ldg(&Pf[(size_t)h.y * 2 + 1]);
        stg_cs_f2(out + (size_t)tok * OUTW + EMBED, pv.x, pv.y);  // cols 64..65
    }

    // ---- Burst-issue all 16 W-row gathers (8B/lane, coalesced 256B rows).
    // Scalars travel via SHFL (ALU pipe), not LSU broadcasts. ----
    float2 a[TPW], b[TPW];
#pragma unroll
    for (int t = 0; t < TPW; t++) {
        const int hx = __shfl_sync(0xffffffffu, h.x, t);
        const int hy = __shfl_sync(0xffffffffu, h.y, t);
        a[t] = __ldg(reinterpret_cast<const float2*>(W + (size_t)hx * EMBED) + lane);
        b[t] = __ldg(reinterpret_cast<const float2*>(W + (size_t)hy * EMBED) + lane);
    }

    // ---- Consume in order (frees a[t]/b[t] early), streaming stores. ----
#pragma unroll
    for (int t = 0; t < TPW; t++) {
        const float px = __shfl_sync(0xffffffffu, pwv.x, t);
        const float py = __shfl_sync(0xffffffffu, pwv.y, t);
        float2 e;
        e.x = fmaf(a[t].x, px, b[t].x * py);
        e.y = fmaf(a[t].y, px, b[t].y * py);
        float* o = out + (size_t)(base + t) * OUTW;   // 264B stride, 8B aligned
        stg_cs_f2(o + lane * 2, e.x, e.y);            // cols 0..63
    }
}

extern "C" void kernel_launch(void* const* d_in, const int* in_sizes, int n_in,
                              void* d_out, int out_size)
{
    const int*    words      = (const int*)d_in[0];
    const int2*   hash_table = (const int2*)d_in[1];
    const float*  W          = (const float*)d_in[2];
    const float2* P          = (const float2*)d_in[3];
    float*        out        = (float*)d_out;

    const int tokens_per_block = (TPB / 32) * TPW;                        // 64
    const int blocks = (NTOK + tokens_per_block - 1) / tokens_per_block;  // 12800
    hash_embedding_kernel<<<blocks, TPB>>>(words, hash_table, W, P, out);
}